// round 12
// baseline (speedup 1.0000x reference)
#include <cuda_runtime.h>
#include <cuda_fp16.h>
#include <mma.h>
#include <math.h>
#include <stdint.h>

using namespace nvcuda;

#define BB 8
#define NN 4096
#define CC 512
#define HH 8
#define DH 64
#define EPSF 1e-12f
#define GNS 4

// gemm smem: rows of 32 fp16 padded to 40 (80B). Stage = A(128) + Bh(256) + Bl(256) rows.
#define SPITCH 40
#define STAGE_E 25600        // 640 rows * 40 elems
#define NSTG 3
#define SMEM_DYN 153600      // 3 stages * 25600 * 2B ; epilogue 128*264*4 = 135168 fits

// ---------------- scratch ----------------
__device__ __half g_x16[16777216];
__device__ __half g_y16[ 8388608];
__device__ __half g_wh [  262144], g_wl [  262144];
__device__ __half g_qwh[  131072], g_qwl[  131072];
__device__ __half g_p16[  262144];
__device__ __half g_k16[16777216];
__device__ __half g_q16[16777216];
__device__ __half g_Tth[ 2097152], g_Ttl[ 2097152];
__device__ __half g_M2h[ 2097152], g_M2l[ 2097152];
__device__ float g_nk_part[GNS * BB * CC];
__device__ float g_nq_part[GNS * BB * CC];
__device__ float g_Spart[GNS * BB * HH * DH * DH];
__device__ float g_attn [BB * HH * DH * DH];

// ---------------- helpers ----------------
__device__ __forceinline__ uint32_t smem_u32(const void* p) {
    uint32_t a;
    asm("{ .reg .u64 t; cvta.to.shared.u64 t, %1; cvt.u32.u64 %0, t; }" : "=r"(a) : "l"(p));
    return a;
}
__device__ __forceinline__ void split2h(float v, __half& h, __half& l) {
    h = __float2half_rn(v);
    l = __float2half_rn(v - __half2float(h));
}
__device__ __forceinline__ uint32_t pack2h(__half a, __half b) {
    return (uint32_t)__half_as_ushort(a) | ((uint32_t)__half_as_ushort(b) << 16);
}
#define CPA16(s, g)  asm volatile("cp.async.cg.shared.global [%0], [%1], 16;" :: "r"(s), "l"(g))
#define CPA_COMMIT() asm volatile("cp.async.commit_group;")
#define CPA_WAIT2()  asm volatile("cp.async.wait_group 2;")
#define CPA_WAIT1()  asm volatile("cp.async.wait_group 1;")
#define CPA_WAIT0()  asm volatile("cp.async.wait_group 0;")

// ---------------- conversions ----------------
__global__ void convh_kernel(const float4* __restrict__ in, uint2* __restrict__ o16, int n4) {
    int i = blockIdx.x * 256 + threadIdx.x;
    if (i < n4) {
        float4 v = in[i];
        o16[i] = make_uint2(pack2h(__float2half_rn(v.x), __float2half_rn(v.y)),
                            pack2h(__float2half_rn(v.z), __float2half_rn(v.w)));
    }
}
__global__ void convhl_kernel(const float4* __restrict__ in,
                              uint2* __restrict__ oh, uint2* __restrict__ ol, int n4) {
    int i = blockIdx.x * 256 + threadIdx.x;
    if (i < n4) {
        float4 v = in[i];
        __half h0, h1, h2, h3, l0, l1, l2, l3;
        split2h(v.x, h0, l0); split2h(v.y, h1, l1);
        split2h(v.z, h2, l2); split2h(v.w, h3, l3);
        oh[i] = make_uint2(pack2h(h0, h1), pack2h(h2, h3));
        ol[i] = make_uint2(pack2h(l0, l1), pack2h(l2, l3));
    }
}

// ---------------- fp16 2-pass split GEMM, CTA 128x256, warp 64x64 ----------------
// C[m,n] = sum_k A[m,k]*B[n,k]; A fp16, B = Bh+Bl.
// mode 0: hi/lo fp16 planes. mode 2: fp32 + bias. mode 3: fp16 plane.
__global__ __launch_bounds__(256, 1)
void gemm_wm(const __half* __restrict__ A, int pA, long long sA,
             const __half* __restrict__ Bh, const __half* __restrict__ Bl,
             int pB, long long sB,
             __half* __restrict__ Ch, __half* __restrict__ Cl,
             float* __restrict__ Cf, int pC, long long sC,
             const float* __restrict__ bias, int K, int mode)
{
    extern __shared__ char smraw[];
    __half* sbf = (__half*)smraw;
    float* sf = (float*)smraw;
    const int t = threadIdx.x;
    const int wid = t >> 5;
    const int bz = blockIdx.z;
    const int m0 = blockIdx.y * 128, n0 = blockIdx.x * 256;
    const int wm = (wid & 1) * 64, wn = (wid >> 1) * 64;   // 2x4 warps of 64x64

    const int prow = t >> 2;        // 0..63
    const int pch  = (t & 3) * 8;   // 8-elem (16B) chunk

    const __half* A_  = A  + (long long)bz * sA + (long long)m0 * pA;
    const __half* Bh_ = Bh + (long long)bz * sB + (long long)n0 * pB;
    const __half* Bl_ = Bl + (long long)bz * sB + (long long)n0 * pB;

    const int nkb = K >> 5;

    auto produce = [&](int s, int kb) {
        const uint32_t sb = smem_u32(sbf + s * STAGE_E);
        #pragma unroll
        for (int u = 0; u < 2; ++u) {
            const int r = prow + u * 64;
            CPA16(sb + (uint32_t)(r * SPITCH + pch) * 2u, A_ + (long long)r * pA + kb + pch);
        }
        #pragma unroll
        for (int u = 0; u < 4; ++u) {
            const int r = prow + u * 64;
            CPA16(sb + (uint32_t)((128 + r) * SPITCH + pch) * 2u, Bh_ + (long long)r * pB + kb + pch);
            CPA16(sb + (uint32_t)((384 + r) * SPITCH + pch) * 2u, Bl_ + (long long)r * pB + kb + pch);
        }
        CPA_COMMIT();
    };

    produce(0, 0);
    if (nkb > 1) produce(1, 32);

    wmma::fragment<wmma::accumulator, 16, 16, 16, float> acc[4][4];
    #pragma unroll
    for (int i = 0; i < 4; ++i)
        #pragma unroll
        for (int j = 0; j < 4; ++j) wmma::fill_fragment(acc[i][j], 0.0f);

    for (int i = 0; i < nkb; ++i) {
        if (i + 2 < nkb) { produce((i + 2) % NSTG, (i + 2) * 32); CPA_WAIT2(); }
        else if (i + 1 < nkb) { CPA_WAIT1(); }
        else { CPA_WAIT0(); }
        __syncthreads();
        const int s = i % NSTG;
        const __half* sa = sbf + s * STAGE_E;
        const __half* sB = sa + 128 * SPITCH;
        const __half* sL = sa + 384 * SPITCH;
        #pragma unroll
        for (int kk = 0; kk < 32; kk += 16) {
            wmma::fragment<wmma::matrix_a, 16, 16, 16, __half, wmma::row_major> fa[4];
            #pragma unroll
            for (int im = 0; im < 4; ++im)
                wmma::load_matrix_sync(fa[im], sa + (wm + im * 16) * SPITCH + kk, SPITCH);
            {
                wmma::fragment<wmma::matrix_b, 16, 16, 16, __half, wmma::col_major> fb[4];
                #pragma unroll
                for (int in_ = 0; in_ < 4; ++in_)
                    wmma::load_matrix_sync(fb[in_], sB + (wn + in_ * 16) * SPITCH + kk, SPITCH);
                #pragma unroll
                for (int im = 0; im < 4; ++im)
                    #pragma unroll
                    for (int in_ = 0; in_ < 4; ++in_)
                        wmma::mma_sync(acc[im][in_], fa[im], fb[in_], acc[im][in_]);
            }
            {
                wmma::fragment<wmma::matrix_b, 16, 16, 16, __half, wmma::col_major> fb[4];
                #pragma unroll
                for (int in_ = 0; in_ < 4; ++in_)
                    wmma::load_matrix_sync(fb[in_], sL + (wn + in_ * 16) * SPITCH + kk, SPITCH);
                #pragma unroll
                for (int im = 0; im < 4; ++im)
                    #pragma unroll
                    for (int in_ = 0; in_ < 4; ++in_)
                        wmma::mma_sync(acc[im][in_], fa[im], fb[in_], acc[im][in_]);
            }
        }
        __syncthreads();
    }

    // ---- epilogue: full 128x256 fp32 tile in smem, pitch 264 ----
    #pragma unroll
    for (int im = 0; im < 4; ++im)
        #pragma unroll
        for (int in_ = 0; in_ < 4; ++in_)
            wmma::store_matrix_sync(sf + (wm + im * 16) * 264 + wn + in_ * 16,
                                    acc[im][in_], 264, wmma::mem_row_major);
    __syncthreads();

    const int row = t >> 1, cb = (t & 1) * 128;   // each thread: 128 cols
    const float* sr = sf + row * 264 + cb;
    if (mode == 0) {
        __half* dh = Ch + (long long)bz * sC + (long long)(m0 + row) * pC + n0 + cb;
        __half* dl = Cl + (long long)bz * sC + (long long)(m0 + row) * pC + n0 + cb;
        #pragma unroll
        for (int j = 0; j < 16; ++j) {
            uint4 hv, lv;
            uint32_t* hp = (uint32_t*)&hv;
            uint32_t* lp = (uint32_t*)&lv;
            #pragma unroll
            for (int e = 0; e < 4; ++e) {
                __half h0, h1, l0, l1;
                split2h(sr[j * 8 + e * 2 + 0], h0, l0);
                split2h(sr[j * 8 + e * 2 + 1], h1, l1);
                hp[e] = pack2h(h0, h1);
                lp[e] = pack2h(l0, l1);
            }
            *(uint4*)(dh + j * 8) = hv;
            *(uint4*)(dl + j * 8) = lv;
        }
    } else if (mode == 3) {
        __half* dh = Ch + (long long)bz * sC + (long long)(m0 + row) * pC + n0 + cb;
        #pragma unroll
        for (int j = 0; j < 16; ++j) {
            uint4 hv;
            uint32_t* hp = (uint32_t*)&hv;
            #pragma unroll
            for (int e = 0; e < 4; ++e)
                hp[e] = pack2h(__float2half_rn(sr[j * 8 + e * 2 + 0]),
                               __float2half_rn(sr[j * 8 + e * 2 + 1]));
            *(uint4*)(dh + j * 8) = hv;
        }
    } else {
        float* dst = Cf + (long long)bz * sC + (long long)(m0 + row) * pC + n0 + cb;
        #pragma unroll
        for (int j = 0; j < 32; ++j) {
            float4 v = make_float4(sr[j * 4 + 0], sr[j * 4 + 1], sr[j * 4 + 2], sr[j * 4 + 3]);
            if (mode == 2) {
                const float* bp = bias + n0 + cb + j * 4;
                v.x += bp[0]; v.y += bp[1]; v.z += bp[2]; v.w += bp[3];
            }
            *(float4*)(dst + j * 4) = v;
        }
    }
}

// ---------------- tensor-core gram + fused sumsq ----------------
__global__ __launch_bounds__(256) void gram_kernel(
    const __half* __restrict__ q16, const __half* __restrict__ k16,
    float* __restrict__ Spart, float* __restrict__ nq_part, float* __restrict__ nk_part)
{
    const int ns = blockIdx.x, h = blockIdx.y, b = blockIdx.z;
    __shared__ __half qs[64 * 72];
    __shared__ __half ks[64 * 72];
    const int t = threadIdx.x;
    const int wid = t >> 5;
    const int wr = wid & 3, wc = wid >> 2;
    const long long base = ((long long)b * NN) * 512 + h * 64;
    const int n0 = ns * (NN / GNS);

    const int lrow  = t >> 3;
    const int lcol8 = (t & 7) * 8;

    wmma::fragment<wmma::accumulator, 16, 16, 16, float> acc[2];
    wmma::fill_fragment(acc[0], 0.0f);
    wmma::fill_fragment(acc[1], 0.0f);
    float sq_q[8], sq_k[8];
    #pragma unroll
    for (int j = 0; j < 8; ++j) { sq_q[j] = 0.f; sq_k[j] = 0.f; }

    for (int ch = 0; ch < (NN / GNS) / 64; ++ch) {
        const int nb = n0 + ch * 64;
        __syncthreads();
        #pragma unroll
        for (int hf = 0; hf < 2; ++hf) {
            const int r = lrow + hf * 32;
            const long long g = base + (long long)(nb + r) * 512 + lcol8;
            uint4 qv = *(const uint4*)(q16 + g);
            uint4 kv = *(const uint4*)(k16 + g);
            *(uint4*)(qs + r * 72 + lcol8) = qv;
            *(uint4*)(ks + r * 72 + lcol8) = kv;
            const __half* qh_ = (const __half*)&qv;
            const __half* kh_ = (const __half*)&kv;
            #pragma unroll
            for (int j = 0; j < 8; ++j) {
                float fq = __half2float(qh_[j]);
                float fk = __half2float(kh_[j]);
                sq_q[j] += fq * fq;
                sq_k[j] += fk * fk;
            }
        }
        __syncthreads();
        #pragma unroll
        for (int nsub = 0; nsub < 4; ++nsub) {
            wmma::fragment<wmma::matrix_a, 16, 16, 16, __half, wmma::col_major> fa;
            wmma::fragment<wmma::matrix_b, 16, 16, 16, __half, wmma::row_major> fb0, fb1;
            wmma::load_matrix_sync(fa,  qs + nsub * 16 * 72 + wr * 16, 72);
            wmma::load_matrix_sync(fb0, ks + nsub * 16 * 72 + wc * 32, 72);
            wmma::load_matrix_sync(fb1, ks + nsub * 16 * 72 + wc * 32 + 16, 72);
            wmma::mma_sync(acc[0], fa, fb0, acc[0]);
            wmma::mma_sync(acc[1], fa, fb1, acc[1]);
        }
    }

    float* dst = Spart + ((((long long)ns * BB + b) * HH + h) * DH) * DH;
    wmma::store_matrix_sync(dst + (wr * 16) * 64 + wc * 32,      acc[0], 64, wmma::mem_row_major);
    wmma::store_matrix_sync(dst + (wr * 16) * 64 + wc * 32 + 16, acc[1], 64, wmma::mem_row_major);

    __syncthreads();
    float* redq = (float*)qs;
    float* redk = (float*)ks;
    #pragma unroll
    for (int j = 0; j < 8; ++j) { redq[t * 8 + j] = sq_q[j]; redk[t * 8 + j] = sq_k[j]; }
    __syncthreads();
    if (t < 64) {
        const int oct = t >> 3, j = t & 7;
        float sq = 0.f, sk = 0.f;
        #pragma unroll
        for (int m = 0; m < 32; ++m) {
            const int tt = m * 8 + oct;
            sq += redq[tt * 8 + j];
            sk += redk[tt * 8 + j];
        }
        nq_part[(ns * BB + b) * CC + h * 64 + t] = sq;
        nk_part[(ns * BB + b) * CC + h * 64 + t] = sk;
    }
}

// ---------------- attn ----------------
__global__ void attn_kernel(
    const float* __restrict__ Spart,
    const float* __restrict__ nq_part, const float* __restrict__ nk_part,
    const float* __restrict__ temp, float* __restrict__ attn)
{
    const int h = blockIdx.x, b = blockIdx.y, d = threadIdx.x;
    __shared__ float snk[64];
    const int c = h * 64 + d;
    float sk = 0.f, sq = 0.f;
    #pragma unroll
    for (int ch = 0; ch < GNS; ++ch) {
        sk += nk_part[(ch * BB + b) * CC + c];
        sq += nq_part[(ch * BB + b) * CC + c];
    }
    snk[d] = fmaxf(sqrtf(sk), EPSF);
    const float nqv = fmaxf(sqrtf(sq), EPSF);
    __syncthreads();
    const float tv = temp[h];
    float vals[64];
    float mx = -1e30f;
    #pragma unroll
    for (int e = 0; e < 64; ++e) {
        float s = 0.f;
        #pragma unroll
        for (int ns = 0; ns < GNS; ++ns)
            s += Spart[((((long long)ns * BB + b) * HH + h) * DH + d) * DH + e];
        float v = s * tv / (nqv * snk[e]);
        vals[e] = v;
        mx = fmaxf(mx, v);
    }
    float sum = 0.f;
    #pragma unroll
    for (int e = 0; e < 64; ++e) { vals[e] = expf(vals[e] - mx); sum += vals[e]; }
    const float inv = 1.0f / sum;
    float* row = attn + (((long long)(b * HH + h) * DH) * DH) + (long long)d * DH;
    #pragma unroll
    for (int e = 0; e < 64; ++e) row[e] = vals[e] * inv;
}

// ---------------- tkern ----------------
__global__ __launch_bounds__(256) void tkern(
    const float* __restrict__ attn, const float* __restrict__ kv_w,
    __half* __restrict__ Tth, __half* __restrict__ Ttl)
{
    const int b = blockIdx.x, h = blockIdx.y;
    __shared__ float AT[64][65];
    const float* Ab = attn + (((long long)(b * HH + h) * DH) * DH);
    for (int i = threadIdx.x; i < 4096; i += 256) AT[i >> 6][i & 63] = Ab[i];
    __syncthreads();
    const float* Wv = kv_w + (long long)(512 + h * 64) * CC;
    for (int half_ = 0; half_ < 2; ++half_) {
        const int c = half_ * 256 + threadIdx.x;
        float acc[64];
        #pragma unroll
        for (int d = 0; d < 64; ++d) acc[d] = 0.f;
        for (int e = 0; e < 64; ++e) {
            const float wv = Wv[(long long)e * CC + c];
            #pragma unroll
            for (int d = 0; d < 64; ++d) acc[d] += AT[d][e] * wv;
        }
        const long long base = ((long long)b * CC + c) * CC + h * 64;
        #pragma unroll
        for (int d = 0; d < 64; d += 2) {
            __half h0, l0, h1, l1;
            split2h(acc[d],     h0, l0);
            split2h(acc[d + 1], h1, l1);
            *(uint32_t*)(Tth + base + d) = pack2h(h0, h1);
            *(uint32_t*)(Ttl + base + d) = pack2h(l0, l1);
        }
    }
}

// ---------------- launch ----------------
extern "C" void kernel_launch(void* const* d_in, const int* in_sizes, int n_in,
                              void* d_out, int out_size)
{
    (void)in_sizes; (void)n_in; (void)out_size;
    const float* x      = (const float*)d_in[0];
    const float* y      = (const float*)d_in[1];
    const float* kv_w   = (const float*)d_in[2];
    const float* q_w    = (const float*)d_in[3];
    const float* proj_w = (const float*)d_in[4];
    const float* proj_b = (const float*)d_in[5];
    const float* temp   = (const float*)d_in[6];
    float* out = (float*)d_out;

    __half *x16, *y16, *wh, *wl, *qwh, *qwl, *p16, *k16, *q16, *Tth, *Ttl, *M2h, *M2l;
    float *nkp, *nqp, *Sp, *ap;
    cudaGetSymbolAddress((void**)&x16, g_x16);
    cudaGetSymbolAddress((void**)&y16, g_y16);
    cudaGetSymbolAddress((void**)&wh,  g_wh);  cudaGetSymbolAddress((void**)&wl,  g_wl);
    cudaGetSymbolAddress((void**)&qwh, g_qwh); cudaGetSymbolAddress((void**)&qwl, g_qwl);
    cudaGetSymbolAddress((void**)&p16, g_p16);
    cudaGetSymbolAddress((void**)&k16, g_k16);
    cudaGetSymbolAddress((void**)&q16, g_q16);
    cudaGetSymbolAddress((void**)&Tth, g_Tth); cudaGetSymbolAddress((void**)&Ttl, g_Ttl);
    cudaGetSymbolAddress((void**)&M2h, g_M2h); cudaGetSymbolAddress((void**)&M2l, g_M2l);
    cudaGetSymbolAddress((void**)&nkp, g_nk_part);
    cudaGetSymbolAddress((void**)&nqp, g_nq_part);
    cudaGetSymbolAddress((void**)&Sp,  g_Spart);
    cudaGetSymbolAddress((void**)&ap,  g_attn);

    cudaFuncSetAttribute(gemm_wm, cudaFuncAttributeMaxDynamicSharedMemorySize, SMEM_DYN);

    // 0) conversions
    convh_kernel<<<16384, 256>>>((const float4*)x,      (uint2*)x16, 4194304);
    convh_kernel<<< 8192, 256>>>((const float4*)y,      (uint2*)y16, 2097152);
    convh_kernel<<<  256, 256>>>((const float4*)proj_w, (uint2*)p16,   65536);
    convhl_kernel<<< 256, 256>>>((const float4*)kv_w,   (uint2*)wh,  (uint2*)wl,  65536);
    convhl_kernel<<< 128, 256>>>((const float4*)q_w,    (uint2*)qwh, (uint2*)qwl, 32768);

    // 1) k = x @ Wk^T -> fp16
    gemm_wm<<<dim3(2, 256, 1), 256, SMEM_DYN>>>(
        x16, 512, 0, wh, wl, 512, 0,
        k16, nullptr, nullptr, 512, 0, nullptr, 512, 3);

    // 2) q = y @ q_w^T -> fp16
    gemm_wm<<<dim3(2, 256, 1), 256, SMEM_DYN>>>(
        y16, 256, 0, qwh, qwl, 256, 0,
        q16, nullptr, nullptr, 512, 0, nullptr, 256, 3);

    // 3) tensor-core Gram + fused sumsq
    gram_kernel<<<dim3(GNS, HH, BB), 256>>>(q16, k16, Sp, nqp, nkp);

    // 4) normalize + softmax
    attn_kernel<<<dim3(HH, BB), 64>>>(Sp, nqp, nkp, temp, ap);

    // 5) Tt
    tkern<<<dim3(BB, HH), 256>>>(ap, kv_w, Tth, Ttl);

    // 6) M2 = proj_w @ Tt^T -> fp16 hi/lo
    gemm_wm<<<dim3(2, 4, BB), 256, SMEM_DYN>>>(
        p16, 512, 0,
        Tth, Ttl, 512, (long long)CC * CC,
        M2h, M2l, nullptr, 512, (long long)CC * CC, nullptr, 512, 0);

    // 7) out = x @ M2^T + bias -> fp32
    gemm_wm<<<dim3(2, 32, BB), 256, SMEM_DYN>>>(
        x16, 512, (long long)NN * 512,
        M2h, M2l, 512, (long long)CC * CC,
        nullptr, nullptr, out, 512, (long long)NN * CC,
        proj_b, 512, 2);
}

// round 13
// speedup vs baseline: 1.1983x; 1.1983x over previous
#include <cuda_runtime.h>
#include <cuda_fp16.h>
#include <mma.h>
#include <math.h>
#include <stdint.h>

using namespace nvcuda;

#define BB 8
#define NN 4096
#define CC 512
#define HH 8
#define DH 64
#define EPSF 1e-12f
#define GNS 4

// gemm smem: rows of 64 fp16 padded to 72 (144B). Stage = A(128)+Bh(128)+Bl(128) rows.
#define SPITCH 72
#define PLANE  9216          // 128*72 elems
#define STAGE_E 27648        // 3 planes
#define SMEM_DYN 110592      // 2 stages * 27648 * 2B ; epilogue 128*132*4 = 67584 fits

// ---------------- scratch ----------------
__device__ __half g_x16[16777216];
__device__ __half g_y16[ 8388608];
__device__ __half g_wh [  262144], g_wl [  262144];
__device__ __half g_qwh[  131072], g_qwl[  131072];
__device__ __half g_p16[  262144];
__device__ __half g_k16[16777216];
__device__ __half g_q16[16777216];
__device__ __half g_Tth[ 2097152], g_Ttl[ 2097152];
__device__ __half g_M2h[ 2097152], g_M2l[ 2097152];
__device__ float g_nk_part[GNS * BB * CC];
__device__ float g_nq_part[GNS * BB * CC];
__device__ float g_Spart[GNS * BB * HH * DH * DH];
__device__ float g_attn [BB * HH * DH * DH];

// ---------------- helpers ----------------
__device__ __forceinline__ uint32_t smem_u32(const void* p) {
    uint32_t a;
    asm("{ .reg .u64 t; cvta.to.shared.u64 t, %1; cvt.u32.u64 %0, t; }" : "=r"(a) : "l"(p));
    return a;
}
__device__ __forceinline__ void split2h(float v, __half& h, __half& l) {
    h = __float2half_rn(v);
    l = __float2half_rn(v - __half2float(h));
}
__device__ __forceinline__ uint32_t pack2h(__half a, __half b) {
    return (uint32_t)__half_as_ushort(a) | ((uint32_t)__half_as_ushort(b) << 16);
}
#define CPA16(s, g)  asm volatile("cp.async.cg.shared.global [%0], [%1], 16;" :: "r"(s), "l"(g))
#define CPA_COMMIT() asm volatile("cp.async.commit_group;")
#define CPA_WAIT1()  asm volatile("cp.async.wait_group 1;")
#define CPA_WAIT0()  asm volatile("cp.async.wait_group 0;")

// ---------------- conversions ----------------
__global__ void convh_kernel(const float4* __restrict__ in, uint2* __restrict__ o16, int n4) {
    int i = blockIdx.x * 256 + threadIdx.x;
    if (i < n4) {
        float4 v = in[i];
        o16[i] = make_uint2(pack2h(__float2half_rn(v.x), __float2half_rn(v.y)),
                            pack2h(__float2half_rn(v.z), __float2half_rn(v.w)));
    }
}
__global__ void convhl_kernel(const float4* __restrict__ in,
                              uint2* __restrict__ oh, uint2* __restrict__ ol, int n4) {
    int i = blockIdx.x * 256 + threadIdx.x;
    if (i < n4) {
        float4 v = in[i];
        __half h0, h1, h2, h3, l0, l1, l2, l3;
        split2h(v.x, h0, l0); split2h(v.y, h1, l1);
        split2h(v.z, h2, l2); split2h(v.w, h3, l3);
        oh[i] = make_uint2(pack2h(h0, h1), pack2h(h2, h3));
        ol[i] = make_uint2(pack2h(l0, l1), pack2h(l2, l3));
    }
}

// ---------------- fp16 2-pass split GEMM, CTA 128x128, warp 64x32, K-stage 64 ----------------
// C[m,n] = sum_k A[m,k]*B[n,k]; A fp16, B = Bh+Bl.
// mode 0: hi/lo fp16 planes. mode 2: fp32 + bias. mode 3: fp16 plane.
__global__ __launch_bounds__(256, 2)
void gemm_wm(const __half* __restrict__ A, int pA, long long sA,
             const __half* __restrict__ Bh, const __half* __restrict__ Bl,
             int pB, long long sB,
             __half* __restrict__ Ch, __half* __restrict__ Cl,
             float* __restrict__ Cf, int pC, long long sC,
             const float* __restrict__ bias, int K, int mode)
{
    extern __shared__ char smraw[];
    __half* sbf = (__half*)smraw;
    float* sf = (float*)smraw;
    const int t = threadIdx.x;
    const int wid = t >> 5;
    const int bz = blockIdx.z;
    const int m0 = blockIdx.y * 128, n0 = blockIdx.x * 128;
    const int wm = (wid & 1) * 64, wn = (wid >> 1) * 32;   // 2x4 warps of 64x32

    const int prow = t >> 3;        // 0..31
    const int pch  = (t & 7) * 8;   // 8-elem (16B) chunk within 64

    const __half* A_  = A  + (long long)bz * sA + (long long)m0 * pA;
    const __half* Bh_ = Bh + (long long)bz * sB + (long long)n0 * pB;
    const __half* Bl_ = Bl + (long long)bz * sB + (long long)n0 * pB;

    const int nkb = K >> 6;   // 64-elem stages

    auto produce = [&](int s, int kb) {
        const uint32_t sb = smem_u32(sbf + s * STAGE_E);
        #pragma unroll
        for (int u = 0; u < 4; ++u) {
            const int r = prow + u * 32;
            CPA16(sb + (uint32_t)(r * SPITCH + pch) * 2u,             A_  + (long long)r * pA + kb + pch);
            CPA16(sb + (uint32_t)((r + 128) * SPITCH + pch) * 2u,     Bh_ + (long long)r * pB + kb + pch);
            CPA16(sb + (uint32_t)((r + 256) * SPITCH + pch) * 2u,     Bl_ + (long long)r * pB + kb + pch);
        }
        CPA_COMMIT();
    };

    produce(0, 0);

    wmma::fragment<wmma::accumulator, 16, 16, 16, float> acc[4][2];
    #pragma unroll
    for (int i = 0; i < 4; ++i)
        #pragma unroll
        for (int j = 0; j < 2; ++j) wmma::fill_fragment(acc[i][j], 0.0f);

    for (int i = 0; i < nkb; ++i) {
        if (i + 1 < nkb) {
            produce((i + 1) & 1, (i + 1) * 64);
            CPA_WAIT1();
        } else {
            CPA_WAIT0();
        }
        __syncthreads();
        const int s = i & 1;
        const __half* sa  = sbf + s * STAGE_E;
        const __half* sbh = sa + PLANE;
        const __half* sbl = sa + 2 * PLANE;
        #pragma unroll
        for (int kk = 0; kk < 64; kk += 16) {
            wmma::fragment<wmma::matrix_a, 16, 16, 16, __half, wmma::row_major> fa[4];
            wmma::fragment<wmma::matrix_b, 16, 16, 16, __half, wmma::col_major> fbh[2], fbl[2];
            #pragma unroll
            for (int im = 0; im < 4; ++im)
                wmma::load_matrix_sync(fa[im], sa + (wm + im * 16) * SPITCH + kk, SPITCH);
            #pragma unroll
            for (int in_ = 0; in_ < 2; ++in_)
                wmma::load_matrix_sync(fbh[in_], sbh + (wn + in_ * 16) * SPITCH + kk, SPITCH);
            #pragma unroll
            for (int im = 0; im < 4; ++im)
                #pragma unroll
                for (int in_ = 0; in_ < 2; ++in_)
                    wmma::mma_sync(acc[im][in_], fa[im], fbh[in_], acc[im][in_]);
            #pragma unroll
            for (int in_ = 0; in_ < 2; ++in_)
                wmma::load_matrix_sync(fbl[in_], sbl + (wn + in_ * 16) * SPITCH + kk, SPITCH);
            #pragma unroll
            for (int im = 0; im < 4; ++im)
                #pragma unroll
                for (int in_ = 0; in_ < 2; ++in_)
                    wmma::mma_sync(acc[im][in_], fa[im], fbl[in_], acc[im][in_]);
        }
        __syncthreads();
    }

    // ---- epilogue via smem (pitch 132) ----
    #pragma unroll
    for (int im = 0; im < 4; ++im)
        #pragma unroll
        for (int in_ = 0; in_ < 2; ++in_)
            wmma::store_matrix_sync(sf + (wm + im * 16) * 132 + wn + in_ * 16,
                                    acc[im][in_], 132, wmma::mem_row_major);
    __syncthreads();

    const int row = t >> 1, half = (t & 1) * 64;
    const float* sr = sf + row * 132 + half;
    if (mode == 0) {
        __half* dh = Ch + (long long)bz * sC + (long long)(m0 + row) * pC + n0 + half;
        __half* dl = Cl + (long long)bz * sC + (long long)(m0 + row) * pC + n0 + half;
        #pragma unroll
        for (int j = 0; j < 8; ++j) {
            uint4 hv, lv;
            uint32_t* hp = (uint32_t*)&hv;
            uint32_t* lp = (uint32_t*)&lv;
            #pragma unroll
            for (int e = 0; e < 4; ++e) {
                __half h0, h1, l0, l1;
                split2h(sr[j * 8 + e * 2 + 0], h0, l0);
                split2h(sr[j * 8 + e * 2 + 1], h1, l1);
                hp[e] = pack2h(h0, h1);
                lp[e] = pack2h(l0, l1);
            }
            *(uint4*)(dh + j * 8) = hv;
            *(uint4*)(dl + j * 8) = lv;
        }
    } else if (mode == 3) {
        __half* dh = Ch + (long long)bz * sC + (long long)(m0 + row) * pC + n0 + half;
        #pragma unroll
        for (int j = 0; j < 8; ++j) {
            uint4 hv;
            uint32_t* hp = (uint32_t*)&hv;
            #pragma unroll
            for (int e = 0; e < 4; ++e)
                hp[e] = pack2h(__float2half_rn(sr[j * 8 + e * 2 + 0]),
                               __float2half_rn(sr[j * 8 + e * 2 + 1]));
            *(uint4*)(dh + j * 8) = hv;
        }
    } else {
        float* dst = Cf + (long long)bz * sC + (long long)(m0 + row) * pC + n0 + half;
        #pragma unroll
        for (int j = 0; j < 16; ++j) {
            float4 v = make_float4(sr[j * 4 + 0], sr[j * 4 + 1], sr[j * 4 + 2], sr[j * 4 + 3]);
            if (mode == 2) {
                const float* bp = bias + n0 + half + j * 4;
                v.x += bp[0]; v.y += bp[1]; v.z += bp[2]; v.w += bp[3];
            }
            *(float4*)(dst + j * 4) = v;
        }
    }
}

// ---------------- tensor-core gram + fused sumsq ----------------
__global__ __launch_bounds__(256) void gram_kernel(
    const __half* __restrict__ q16, const __half* __restrict__ k16,
    float* __restrict__ Spart, float* __restrict__ nq_part, float* __restrict__ nk_part)
{
    const int ns = blockIdx.x, h = blockIdx.y, b = blockIdx.z;
    __shared__ __half qs[64 * 72];
    __shared__ __half ks[64 * 72];
    const int t = threadIdx.x;
    const int wid = t >> 5;
    const int wr = wid & 3, wc = wid >> 2;
    const long long base = ((long long)b * NN) * 512 + h * 64;
    const int n0 = ns * (NN / GNS);

    const int lrow  = t >> 3;
    const int lcol8 = (t & 7) * 8;

    wmma::fragment<wmma::accumulator, 16, 16, 16, float> acc[2];
    wmma::fill_fragment(acc[0], 0.0f);
    wmma::fill_fragment(acc[1], 0.0f);
    float sq_q[8], sq_k[8];
    #pragma unroll
    for (int j = 0; j < 8; ++j) { sq_q[j] = 0.f; sq_k[j] = 0.f; }

    for (int ch = 0; ch < (NN / GNS) / 64; ++ch) {
        const int nb = n0 + ch * 64;
        __syncthreads();
        #pragma unroll
        for (int hf = 0; hf < 2; ++hf) {
            const int r = lrow + hf * 32;
            const long long g = base + (long long)(nb + r) * 512 + lcol8;
            uint4 qv = *(const uint4*)(q16 + g);
            uint4 kv = *(const uint4*)(k16 + g);
            *(uint4*)(qs + r * 72 + lcol8) = qv;
            *(uint4*)(ks + r * 72 + lcol8) = kv;
            const __half* qh_ = (const __half*)&qv;
            const __half* kh_ = (const __half*)&kv;
            #pragma unroll
            for (int j = 0; j < 8; ++j) {
                float fq = __half2float(qh_[j]);
                float fk = __half2float(kh_[j]);
                sq_q[j] += fq * fq;
                sq_k[j] += fk * fk;
            }
        }
        __syncthreads();
        #pragma unroll
        for (int nsub = 0; nsub < 4; ++nsub) {
            wmma::fragment<wmma::matrix_a, 16, 16, 16, __half, wmma::col_major> fa;
            wmma::fragment<wmma::matrix_b, 16, 16, 16, __half, wmma::row_major> fb0, fb1;
            wmma::load_matrix_sync(fa,  qs + nsub * 16 * 72 + wr * 16, 72);
            wmma::load_matrix_sync(fb0, ks + nsub * 16 * 72 + wc * 32, 72);
            wmma::load_matrix_sync(fb1, ks + nsub * 16 * 72 + wc * 32 + 16, 72);
            wmma::mma_sync(acc[0], fa, fb0, acc[0]);
            wmma::mma_sync(acc[1], fa, fb1, acc[1]);
        }
    }

    float* dst = Spart + ((((long long)ns * BB + b) * HH + h) * DH) * DH;
    wmma::store_matrix_sync(dst + (wr * 16) * 64 + wc * 32,      acc[0], 64, wmma::mem_row_major);
    wmma::store_matrix_sync(dst + (wr * 16) * 64 + wc * 32 + 16, acc[1], 64, wmma::mem_row_major);

    __syncthreads();
    float* redq = (float*)qs;
    float* redk = (float*)ks;
    #pragma unroll
    for (int j = 0; j < 8; ++j) { redq[t * 8 + j] = sq_q[j]; redk[t * 8 + j] = sq_k[j]; }
    __syncthreads();
    if (t < 64) {
        const int oct = t >> 3, j = t & 7;
        float sq = 0.f, sk = 0.f;
        #pragma unroll
        for (int m = 0; m < 32; ++m) {
            const int tt = m * 8 + oct;
            sq += redq[tt * 8 + j];
            sk += redk[tt * 8 + j];
        }
        nq_part[(ns * BB + b) * CC + h * 64 + t] = sq;
        nk_part[(ns * BB + b) * CC + h * 64 + t] = sk;
    }
}

// ---------------- attn ----------------
__global__ void attn_kernel(
    const float* __restrict__ Spart,
    const float* __restrict__ nq_part, const float* __restrict__ nk_part,
    const float* __restrict__ temp, float* __restrict__ attn)
{
    const int h = blockIdx.x, b = blockIdx.y, d = threadIdx.x;
    __shared__ float snk[64];
    const int c = h * 64 + d;
    float sk = 0.f, sq = 0.f;
    #pragma unroll
    for (int ch = 0; ch < GNS; ++ch) {
        sk += nk_part[(ch * BB + b) * CC + c];
        sq += nq_part[(ch * BB + b) * CC + c];
    }
    snk[d] = fmaxf(sqrtf(sk), EPSF);
    const float nqv = fmaxf(sqrtf(sq), EPSF);
    __syncthreads();
    const float tv = temp[h];
    float vals[64];
    float mx = -1e30f;
    #pragma unroll
    for (int e = 0; e < 64; ++e) {
        float s = 0.f;
        #pragma unroll
        for (int ns = 0; ns < GNS; ++ns)
            s += Spart[((((long long)ns * BB + b) * HH + h) * DH + d) * DH + e];
        float v = s * tv / (nqv * snk[e]);
        vals[e] = v;
        mx = fmaxf(mx, v);
    }
    float sum = 0.f;
    #pragma unroll
    for (int e = 0; e < 64; ++e) { vals[e] = expf(vals[e] - mx); sum += vals[e]; }
    const float inv = 1.0f / sum;
    float* row = attn + (((long long)(b * HH + h) * DH) * DH) + (long long)d * DH;
    #pragma unroll
    for (int e = 0; e < 64; ++e) row[e] = vals[e] * inv;
}

// ---------------- tkern ----------------
__global__ __launch_bounds__(256) void tkern(
    const float* __restrict__ attn, const float* __restrict__ kv_w,
    __half* __restrict__ Tth, __half* __restrict__ Ttl)
{
    const int b = blockIdx.x, h = blockIdx.y;
    __shared__ float AT[64][65];
    const float* Ab = attn + (((long long)(b * HH + h) * DH) * DH);
    for (int i = threadIdx.x; i < 4096; i += 256) AT[i >> 6][i & 63] = Ab[i];
    __syncthreads();
    const float* Wv = kv_w + (long long)(512 + h * 64) * CC;
    for (int half_ = 0; half_ < 2; ++half_) {
        const int c = half_ * 256 + threadIdx.x;
        float acc[64];
        #pragma unroll
        for (int d = 0; d < 64; ++d) acc[d] = 0.f;
        for (int e = 0; e < 64; ++e) {
            const float wv = Wv[(long long)e * CC + c];
            #pragma unroll
            for (int d = 0; d < 64; ++d) acc[d] += AT[d][e] * wv;
        }
        const long long base = ((long long)b * CC + c) * CC + h * 64;
        #pragma unroll
        for (int d = 0; d < 64; d += 2) {
            __half h0, l0, h1, l1;
            split2h(acc[d],     h0, l0);
            split2h(acc[d + 1], h1, l1);
            *(uint32_t*)(Tth + base + d) = pack2h(h0, h1);
            *(uint32_t*)(Ttl + base + d) = pack2h(l0, l1);
        }
    }
}

// ---------------- launch ----------------
extern "C" void kernel_launch(void* const* d_in, const int* in_sizes, int n_in,
                              void* d_out, int out_size)
{
    (void)in_sizes; (void)n_in; (void)out_size;
    const float* x      = (const float*)d_in[0];
    const float* y      = (const float*)d_in[1];
    const float* kv_w   = (const float*)d_in[2];
    const float* q_w    = (const float*)d_in[3];
    const float* proj_w = (const float*)d_in[4];
    const float* proj_b = (const float*)d_in[5];
    const float* temp   = (const float*)d_in[6];
    float* out = (float*)d_out;

    __half *x16, *y16, *wh, *wl, *qwh, *qwl, *p16, *k16, *q16, *Tth, *Ttl, *M2h, *M2l;
    float *nkp, *nqp, *Sp, *ap;
    cudaGetSymbolAddress((void**)&x16, g_x16);
    cudaGetSymbolAddress((void**)&y16, g_y16);
    cudaGetSymbolAddress((void**)&wh,  g_wh);  cudaGetSymbolAddress((void**)&wl,  g_wl);
    cudaGetSymbolAddress((void**)&qwh, g_qwh); cudaGetSymbolAddress((void**)&qwl, g_qwl);
    cudaGetSymbolAddress((void**)&p16, g_p16);
    cudaGetSymbolAddress((void**)&k16, g_k16);
    cudaGetSymbolAddress((void**)&q16, g_q16);
    cudaGetSymbolAddress((void**)&Tth, g_Tth); cudaGetSymbolAddress((void**)&Ttl, g_Ttl);
    cudaGetSymbolAddress((void**)&M2h, g_M2h); cudaGetSymbolAddress((void**)&M2l, g_M2l);
    cudaGetSymbolAddress((void**)&nkp, g_nk_part);
    cudaGetSymbolAddress((void**)&nqp, g_nq_part);
    cudaGetSymbolAddress((void**)&Sp,  g_Spart);
    cudaGetSymbolAddress((void**)&ap,  g_attn);

    cudaFuncSetAttribute(gemm_wm, cudaFuncAttributeMaxDynamicSharedMemorySize, SMEM_DYN);

    // 0) conversions
    convh_kernel<<<16384, 256>>>((const float4*)x,      (uint2*)x16, 4194304);
    convh_kernel<<< 8192, 256>>>((const float4*)y,      (uint2*)y16, 2097152);
    convh_kernel<<<  256, 256>>>((const float4*)proj_w, (uint2*)p16,   65536);
    convhl_kernel<<< 256, 256>>>((const float4*)kv_w,   (uint2*)wh,  (uint2*)wl,  65536);
    convhl_kernel<<< 128, 256>>>((const float4*)q_w,    (uint2*)qwh, (uint2*)qwl, 32768);

    // 1) k = x @ Wk^T -> fp16
    gemm_wm<<<dim3(4, 256, 1), 256, SMEM_DYN>>>(
        x16, 512, 0, wh, wl, 512, 0,
        k16, nullptr, nullptr, 512, 0, nullptr, 512, 3);

    // 2) q = y @ q_w^T -> fp16
    gemm_wm<<<dim3(4, 256, 1), 256, SMEM_DYN>>>(
        y16, 256, 0, qwh, qwl, 256, 0,
        q16, nullptr, nullptr, 512, 0, nullptr, 256, 3);

    // 3) tensor-core Gram + fused sumsq
    gram_kernel<<<dim3(GNS, HH, BB), 256>>>(q16, k16, Sp, nqp, nkp);

    // 4) normalize + softmax
    attn_kernel<<<dim3(HH, BB), 64>>>(Sp, nqp, nkp, temp, ap);

    // 5) Tt
    tkern<<<dim3(BB, HH), 256>>>(ap, kv_w, Tth, Ttl);

    // 6) M2 = proj_w @ Tt^T -> fp16 hi/lo
    gemm_wm<<<dim3(4, 4, BB), 256, SMEM_DYN>>>(
        p16, 512, 0,
        Tth, Ttl, 512, (long long)CC * CC,
        M2h, M2l, nullptr, 512, (long long)CC * CC, nullptr, 512, 0);

    // 7) out = x @ M2^T + bias -> fp32
    gemm_wm<<<dim3(4, 32, BB), 256, SMEM_DYN>>>(
        x16, 512, (long long)NN * 512,
        M2h, M2l, 512, (long long)CC * CC,
        nullptr, nullptr, out, 512, (long long)NN * CC,
        proj_b, 512, 2);
}

// round 14
// speedup vs baseline: 1.3412x; 1.1192x over previous
#include <cuda_runtime.h>
#include <cuda_fp16.h>
#include <mma.h>
#include <math.h>
#include <stdint.h>

using namespace nvcuda;

#define BB 8
#define NN 4096
#define CC 512
#define HH 8
#define DH 64
#define EPSF 1e-12f
#define GNS 4

// gemm smem: rows of 64 fp16 padded to 72 (144B). Stage = A(128)+Bh(128)+Bl(128) rows.
#define SPITCH 72
#define PLANE  9216          // 128*72 elems
#define STAGE_E 27648        // 3 planes
#define SMEM_DYN 110592      // 2 stages * 27648 * 2B ; epilogue 128*132*4 = 67584 fits

// ---------------- scratch ----------------
__device__ __half g_x16[16777216];
__device__ __half g_y16[ 8388608];
__device__ __half g_w16[  262144];    // kv_w k-rows fp16 [512,512]
__device__ __half g_qw16[ 131072];    // q_w fp16 [512,256]
__device__ __half g_p16[  262144];
__device__ __half g_k16[16777216];
__device__ __half g_q16[16777216];
__device__ __half g_Tth[ 2097152], g_Ttl[ 2097152];
__device__ __half g_M2h[ 2097152], g_M2l[ 2097152];
__device__ float g_nk_part[GNS * BB * CC];
__device__ float g_nq_part[GNS * BB * CC];
__device__ float g_Spart[GNS * BB * HH * DH * DH];
__device__ float g_attn [BB * HH * DH * DH];

// ---------------- helpers ----------------
__device__ __forceinline__ uint32_t smem_u32(const void* p) {
    uint32_t a;
    asm("{ .reg .u64 t; cvta.to.shared.u64 t, %1; cvt.u32.u64 %0, t; }" : "=r"(a) : "l"(p));
    return a;
}
__device__ __forceinline__ void split2h(float v, __half& h, __half& l) {
    h = __float2half_rn(v);
    l = __float2half_rn(v - __half2float(h));
}
__device__ __forceinline__ uint32_t pack2h(__half a, __half b) {
    return (uint32_t)__half_as_ushort(a) | ((uint32_t)__half_as_ushort(b) << 16);
}
#define CPA16(s, g)  asm volatile("cp.async.cg.shared.global [%0], [%1], 16;" :: "r"(s), "l"(g))
#define CPA_COMMIT() asm volatile("cp.async.commit_group;")
#define CPA_WAIT1()  asm volatile("cp.async.wait_group 1;")
#define CPA_WAIT0()  asm volatile("cp.async.wait_group 0;")

// ---------------- conversions ----------------
__global__ void convh_kernel(const float4* __restrict__ in, uint2* __restrict__ o16, int n4) {
    int i = blockIdx.x * 256 + threadIdx.x;
    if (i < n4) {
        float4 v = in[i];
        o16[i] = make_uint2(pack2h(__float2half_rn(v.x), __float2half_rn(v.y)),
                            pack2h(__float2half_rn(v.z), __float2half_rn(v.w)));
    }
}

// ---------------- fp16 split GEMM, CTA 128x128, warp 64x32, K-stage 64 ----------------
// C[m,n] = sum_k A[m,k]*B[n,k]; A fp16; B = Bh (+ Bl if non-null, 2-pass split).
// mode 0: hi/lo fp16 planes. mode 2: fp32 + bias. mode 3: fp16 plane.
__global__ __launch_bounds__(256, 2)
void gemm_wm(const __half* __restrict__ A, int pA, long long sA,
             const __half* __restrict__ Bh, const __half* __restrict__ Bl,
             int pB, long long sB,
             __half* __restrict__ Ch, __half* __restrict__ Cl,
             float* __restrict__ Cf, int pC, long long sC,
             const float* __restrict__ bias, int K, int mode)
{
    extern __shared__ char smraw[];
    __half* sbf = (__half*)smraw;
    float* sf = (float*)smraw;
    const int t = threadIdx.x;
    const int wid = t >> 5;
    const int bz = blockIdx.z;
    const int m0 = blockIdx.y * 128, n0 = blockIdx.x * 128;
    const int wm = (wid & 1) * 64, wn = (wid >> 1) * 32;   // 2x4 warps of 64x32

    const int prow = t >> 3;        // 0..31
    const int pch  = (t & 7) * 8;   // 8-elem (16B) chunk within 64

    const bool twop = (Bl != nullptr);
    const __half* A_  = A  + (long long)bz * sA + (long long)m0 * pA;
    const __half* Bh_ = Bh + (long long)bz * sB + (long long)n0 * pB;
    const __half* Bl_ = twop ? (Bl + (long long)bz * sB + (long long)n0 * pB) : nullptr;

    const int nkb = K >> 6;   // 64-elem stages

    auto produce = [&](int s, int kb) {
        const uint32_t sb = smem_u32(sbf + s * STAGE_E);
        #pragma unroll
        for (int u = 0; u < 4; ++u) {
            const int r = prow + u * 32;
            CPA16(sb + (uint32_t)(r * SPITCH + pch) * 2u,         A_  + (long long)r * pA + kb + pch);
            CPA16(sb + (uint32_t)((r + 128) * SPITCH + pch) * 2u, Bh_ + (long long)r * pB + kb + pch);
            if (twop)
                CPA16(sb + (uint32_t)((r + 256) * SPITCH + pch) * 2u, Bl_ + (long long)r * pB + kb + pch);
        }
        CPA_COMMIT();
    };

    produce(0, 0);

    wmma::fragment<wmma::accumulator, 16, 16, 16, float> acc[4][2];
    #pragma unroll
    for (int i = 0; i < 4; ++i)
        #pragma unroll
        for (int j = 0; j < 2; ++j) wmma::fill_fragment(acc[i][j], 0.0f);

    for (int i = 0; i < nkb; ++i) {
        if (i + 1 < nkb) {
            produce((i + 1) & 1, (i + 1) * 64);
            CPA_WAIT1();
        } else {
            CPA_WAIT0();
        }
        __syncthreads();
        const int s = i & 1;
        const __half* sa  = sbf + s * STAGE_E;
        const __half* sbh = sa + PLANE;
        const __half* sbl = sa + 2 * PLANE;
        #pragma unroll
        for (int kk = 0; kk < 64; kk += 16) {
            wmma::fragment<wmma::matrix_a, 16, 16, 16, __half, wmma::row_major> fa[4];
            wmma::fragment<wmma::matrix_b, 16, 16, 16, __half, wmma::col_major> fbh[2], fbl[2];
            #pragma unroll
            for (int im = 0; im < 4; ++im)
                wmma::load_matrix_sync(fa[im], sa + (wm + im * 16) * SPITCH + kk, SPITCH);
            #pragma unroll
            for (int in_ = 0; in_ < 2; ++in_)
                wmma::load_matrix_sync(fbh[in_], sbh + (wn + in_ * 16) * SPITCH + kk, SPITCH);
            #pragma unroll
            for (int im = 0; im < 4; ++im)
                #pragma unroll
                for (int in_ = 0; in_ < 2; ++in_)
                    wmma::mma_sync(acc[im][in_], fa[im], fbh[in_], acc[im][in_]);
            if (twop) {
                #pragma unroll
                for (int in_ = 0; in_ < 2; ++in_)
                    wmma::load_matrix_sync(fbl[in_], sbl + (wn + in_ * 16) * SPITCH + kk, SPITCH);
                #pragma unroll
                for (int im = 0; im < 4; ++im)
                    #pragma unroll
                    for (int in_ = 0; in_ < 2; ++in_)
                        wmma::mma_sync(acc[im][in_], fa[im], fbl[in_], acc[im][in_]);
            }
        }
        __syncthreads();
    }

    // ---- epilogue via smem (pitch 132) ----
    #pragma unroll
    for (int im = 0; im < 4; ++im)
        #pragma unroll
        for (int in_ = 0; in_ < 2; ++in_)
            wmma::store_matrix_sync(sf + (wm + im * 16) * 132 + wn + in_ * 16,
                                    acc[im][in_], 132, wmma::mem_row_major);
    __syncthreads();

    const int row = t >> 1, half = (t & 1) * 64;
    const float* sr = sf + row * 132 + half;
    if (mode == 0) {
        __half* dh = Ch + (long long)bz * sC + (long long)(m0 + row) * pC + n0 + half;
        __half* dl = Cl + (long long)bz * sC + (long long)(m0 + row) * pC + n0 + half;
        #pragma unroll
        for (int j = 0; j < 8; ++j) {
            uint4 hv, lv;
            uint32_t* hp = (uint32_t*)&hv;
            uint32_t* lp = (uint32_t*)&lv;
            #pragma unroll
            for (int e = 0; e < 4; ++e) {
                __half h0, h1, l0, l1;
                split2h(sr[j * 8 + e * 2 + 0], h0, l0);
                split2h(sr[j * 8 + e * 2 + 1], h1, l1);
                hp[e] = pack2h(h0, h1);
                lp[e] = pack2h(l0, l1);
            }
            *(uint4*)(dh + j * 8) = hv;
            *(uint4*)(dl + j * 8) = lv;
        }
    } else if (mode == 3) {
        __half* dh = Ch + (long long)bz * sC + (long long)(m0 + row) * pC + n0 + half;
        #pragma unroll
        for (int j = 0; j < 8; ++j) {
            uint4 hv;
            uint32_t* hp = (uint32_t*)&hv;
            #pragma unroll
            for (int e = 0; e < 4; ++e)
                hp[e] = pack2h(__float2half_rn(sr[j * 8 + e * 2 + 0]),
                               __float2half_rn(sr[j * 8 + e * 2 + 1]));
            *(uint4*)(dh + j * 8) = hv;
        }
    } else {
        float* dst = Cf + (long long)bz * sC + (long long)(m0 + row) * pC + n0 + half;
        #pragma unroll
        for (int j = 0; j < 16; ++j) {
            float4 v = make_float4(sr[j * 4 + 0], sr[j * 4 + 1], sr[j * 4 + 2], sr[j * 4 + 3]);
            if (mode == 2) {
                const float* bp = bias + n0 + half + j * 4;
                v.x += bp[0]; v.y += bp[1]; v.z += bp[2]; v.w += bp[3];
            }
            *(float4*)(dst + j * 4) = v;
        }
    }
}

// ---------------- tensor-core gram + fused sumsq ----------------
__global__ __launch_bounds__(256) void gram_kernel(
    const __half* __restrict__ q16, const __half* __restrict__ k16,
    float* __restrict__ Spart, float* __restrict__ nq_part, float* __restrict__ nk_part)
{
    const int ns = blockIdx.x, h = blockIdx.y, b = blockIdx.z;
    __shared__ __half qs[64 * 72];
    __shared__ __half ks[64 * 72];
    const int t = threadIdx.x;
    const int wid = t >> 5;
    const int wr = wid & 3, wc = wid >> 2;
    const long long base = ((long long)b * NN) * 512 + h * 64;
    const int n0 = ns * (NN / GNS);

    const int lrow  = t >> 3;
    const int lcol8 = (t & 7) * 8;

    wmma::fragment<wmma::accumulator, 16, 16, 16, float> acc[2];
    wmma::fill_fragment(acc[0], 0.0f);
    wmma::fill_fragment(acc[1], 0.0f);
    float sq_q[8], sq_k[8];
    #pragma unroll
    for (int j = 0; j < 8; ++j) { sq_q[j] = 0.f; sq_k[j] = 0.f; }

    for (int ch = 0; ch < (NN / GNS) / 64; ++ch) {
        const int nb = n0 + ch * 64;
        __syncthreads();
        #pragma unroll
        for (int hf = 0; hf < 2; ++hf) {
            const int r = lrow + hf * 32;
            const long long g = base + (long long)(nb + r) * 512 + lcol8;
            uint4 qv = *(const uint4*)(q16 + g);
            uint4 kv = *(const uint4*)(k16 + g);
            *(uint4*)(qs + r * 72 + lcol8) = qv;
            *(uint4*)(ks + r * 72 + lcol8) = kv;
            const __half* qh_ = (const __half*)&qv;
            const __half* kh_ = (const __half*)&kv;
            #pragma unroll
            for (int j = 0; j < 8; ++j) {
                float fq = __half2float(qh_[j]);
                float fk = __half2float(kh_[j]);
                sq_q[j] += fq * fq;
                sq_k[j] += fk * fk;
            }
        }
        __syncthreads();
        #pragma unroll
        for (int nsub = 0; nsub < 4; ++nsub) {
            wmma::fragment<wmma::matrix_a, 16, 16, 16, __half, wmma::col_major> fa;
            wmma::fragment<wmma::matrix_b, 16, 16, 16, __half, wmma::row_major> fb0, fb1;
            wmma::load_matrix_sync(fa,  qs + nsub * 16 * 72 + wr * 16, 72);
            wmma::load_matrix_sync(fb0, ks + nsub * 16 * 72 + wc * 32, 72);
            wmma::load_matrix_sync(fb1, ks + nsub * 16 * 72 + wc * 32 + 16, 72);
            wmma::mma_sync(acc[0], fa, fb0, acc[0]);
            wmma::mma_sync(acc[1], fa, fb1, acc[1]);
        }
    }

    float* dst = Spart + ((((long long)ns * BB + b) * HH + h) * DH) * DH;
    wmma::store_matrix_sync(dst + (wr * 16) * 64 + wc * 32,      acc[0], 64, wmma::mem_row_major);
    wmma::store_matrix_sync(dst + (wr * 16) * 64 + wc * 32 + 16, acc[1], 64, wmma::mem_row_major);

    __syncthreads();
    float* redq = (float*)qs;
    float* redk = (float*)ks;
    #pragma unroll
    for (int j = 0; j < 8; ++j) { redq[t * 8 + j] = sq_q[j]; redk[t * 8 + j] = sq_k[j]; }
    __syncthreads();
    if (t < 64) {
        const int oct = t >> 3, j = t & 7;
        float sq = 0.f, sk = 0.f;
        #pragma unroll
        for (int m = 0; m < 32; ++m) {
            const int tt = m * 8 + oct;
            sq += redq[tt * 8 + j];
            sk += redk[tt * 8 + j];
        }
        nq_part[(ns * BB + b) * CC + h * 64 + t] = sq;
        nk_part[(ns * BB + b) * CC + h * 64 + t] = sk;
    }
}

// ---------------- attn ----------------
__global__ void attn_kernel(
    const float* __restrict__ Spart,
    const float* __restrict__ nq_part, const float* __restrict__ nk_part,
    const float* __restrict__ temp, float* __restrict__ attn)
{
    const int h = blockIdx.x, b = blockIdx.y, d = threadIdx.x;
    __shared__ float snk[64];
    const int c = h * 64 + d;
    float sk = 0.f, sq = 0.f;
    #pragma unroll
    for (int ch = 0; ch < GNS; ++ch) {
        sk += nk_part[(ch * BB + b) * CC + c];
        sq += nq_part[(ch * BB + b) * CC + c];
    }
    snk[d] = fmaxf(sqrtf(sk), EPSF);
    const float nqv = fmaxf(sqrtf(sq), EPSF);
    __syncthreads();
    const float tv = temp[h];
    float vals[64];
    float mx = -1e30f;
    #pragma unroll
    for (int e = 0; e < 64; ++e) {
        float s = 0.f;
        #pragma unroll
        for (int ns = 0; ns < GNS; ++ns)
            s += Spart[((((long long)ns * BB + b) * HH + h) * DH + d) * DH + e];
        float v = s * tv / (nqv * snk[e]);
        vals[e] = v;
        mx = fmaxf(mx, v);
    }
    float sum = 0.f;
    #pragma unroll
    for (int e = 0; e < 64; ++e) { vals[e] = expf(vals[e] - mx); sum += vals[e]; }
    const float inv = 1.0f / sum;
    float* row = attn + (((long long)(b * HH + h) * DH) * DH) + (long long)d * DH;
    #pragma unroll
    for (int e = 0; e < 64; ++e) row[e] = vals[e] * inv;
}

// ---------------- tkern ----------------
__global__ __launch_bounds__(256) void tkern(
    const float* __restrict__ attn, const float* __restrict__ kv_w,
    __half* __restrict__ Tth, __half* __restrict__ Ttl)
{
    const int b = blockIdx.x, h = blockIdx.y;
    __shared__ float AT[64][65];
    const float* Ab = attn + (((long long)(b * HH + h) * DH) * DH);
    for (int i = threadIdx.x; i < 4096; i += 256) AT[i >> 6][i & 63] = Ab[i];
    __syncthreads();
    const float* Wv = kv_w + (long long)(512 + h * 64) * CC;
    for (int half_ = 0; half_ < 2; ++half_) {
        const int c = half_ * 256 + threadIdx.x;
        float acc[64];
        #pragma unroll
        for (int d = 0; d < 64; ++d) acc[d] = 0.f;
        for (int e = 0; e < 64; ++e) {
            const float wv = Wv[(long long)e * CC + c];
            #pragma unroll
            for (int d = 0; d < 64; ++d) acc[d] += AT[d][e] * wv;
        }
        const long long base = ((long long)b * CC + c) * CC + h * 64;
        #pragma unroll
        for (int d = 0; d < 64; d += 2) {
            __half h0, l0, h1, l1;
            split2h(acc[d],     h0, l0);
            split2h(acc[d + 1], h1, l1);
            *(uint32_t*)(Tth + base + d) = pack2h(h0, h1);
            *(uint32_t*)(Ttl + base + d) = pack2h(l0, l1);
        }
    }
}

// ---------------- launch ----------------
extern "C" void kernel_launch(void* const* d_in, const int* in_sizes, int n_in,
                              void* d_out, int out_size)
{
    (void)in_sizes; (void)n_in; (void)out_size;
    const float* x      = (const float*)d_in[0];
    const float* y      = (const float*)d_in[1];
    const float* kv_w   = (const float*)d_in[2];
    const float* q_w    = (const float*)d_in[3];
    const float* proj_w = (const float*)d_in[4];
    const float* proj_b = (const float*)d_in[5];
    const float* temp   = (const float*)d_in[6];
    float* out = (float*)d_out;

    __half *x16, *y16, *w16, *qw16, *p16, *k16, *q16, *Tth, *Ttl, *M2h, *M2l;
    float *nkp, *nqp, *Sp, *ap;
    cudaGetSymbolAddress((void**)&x16,  g_x16);
    cudaGetSymbolAddress((void**)&y16,  g_y16);
    cudaGetSymbolAddress((void**)&w16,  g_w16);
    cudaGetSymbolAddress((void**)&qw16, g_qw16);
    cudaGetSymbolAddress((void**)&p16,  g_p16);
    cudaGetSymbolAddress((void**)&k16,  g_k16);
    cudaGetSymbolAddress((void**)&q16,  g_q16);
    cudaGetSymbolAddress((void**)&Tth,  g_Tth); cudaGetSymbolAddress((void**)&Ttl, g_Ttl);
    cudaGetSymbolAddress((void**)&M2h,  g_M2h); cudaGetSymbolAddress((void**)&M2l, g_M2l);
    cudaGetSymbolAddress((void**)&nkp,  g_nk_part);
    cudaGetSymbolAddress((void**)&nqp,  g_nq_part);
    cudaGetSymbolAddress((void**)&Sp,   g_Spart);
    cudaGetSymbolAddress((void**)&ap,   g_attn);

    cudaFuncSetAttribute(gemm_wm, cudaFuncAttributeMaxDynamicSharedMemorySize, SMEM_DYN);

    // 0) conversions (all plain fp16; split planes for Tt/M2 are made by tkern/gemm)
    convh_kernel<<<16384, 256>>>((const float4*)x,      (uint2*)x16,  4194304);
    convh_kernel<<< 8192, 256>>>((const float4*)y,      (uint2*)y16,  2097152);
    convh_kernel<<<  256, 256>>>((const float4*)proj_w, (uint2*)p16,    65536);
    convh_kernel<<<  256, 256>>>((const float4*)kv_w,   (uint2*)w16,    65536);  // k rows only
    convh_kernel<<<  128, 256>>>((const float4*)q_w,    (uint2*)qw16,   32768);

    // 1) k = x @ Wk^T -> fp16   (single pass: k feeds only the logit path)
    gemm_wm<<<dim3(4, 256, 1), 256, SMEM_DYN>>>(
        x16, 512, 0, w16, nullptr, 512, 0,
        k16, nullptr, nullptr, 512, 0, nullptr, 512, 3);

    // 2) q = y @ q_w^T -> fp16  (single pass)
    gemm_wm<<<dim3(4, 256, 1), 256, SMEM_DYN>>>(
        y16, 256, 0, qw16, nullptr, 256, 0,
        q16, nullptr, nullptr, 512, 0, nullptr, 256, 3);

    // 3) tensor-core Gram + fused sumsq
    gram_kernel<<<dim3(GNS, HH, BB), 256>>>(q16, k16, Sp, nqp, nkp);

    // 4) normalize + softmax
    attn_kernel<<<dim3(HH, BB), 64>>>(Sp, nqp, nkp, temp, ap);

    // 5) Tt (fp32 attn x fp32 Wv -> split planes; precision-critical path)
    tkern<<<dim3(BB, HH), 256>>>(ap, kv_w, Tth, Ttl);

    // 6) M2 = proj_w @ Tt^T -> fp16 hi/lo (2-pass)
    gemm_wm<<<dim3(4, 4, BB), 256, SMEM_DYN>>>(
        p16, 512, 0,
        Tth, Ttl, 512, (long long)CC * CC,
        M2h, M2l, nullptr, 512, (long long)CC * CC, nullptr, 512, 0);

    // 7) out = x @ M2^T + bias -> fp32 (2-pass; output precision path)
    gemm_wm<<<dim3(4, 32, BB), 256, SMEM_DYN>>>(
        x16, 512, (long long)NN * 512,
        M2h, M2l, 512, (long long)CC * CC,
        nullptr, nullptr, out, 512, (long long)NN * CC,
        proj_b, 512, 2);
}

// round 17
// speedup vs baseline: 1.4568x; 1.0862x over previous
#include <cuda_runtime.h>
#include <cuda_fp16.h>
#include <mma.h>
#include <math.h>
#include <stdint.h>

using namespace nvcuda;

#define BB 8
#define NN 4096
#define CC 512
#define HH 8
#define DH 64
#define EPSF 1e-12f
#define GNS 4

// gemm smem: rows of 64 fp16 padded to 72 (144B). Stage = A(128)+Bh(128)+Bl(128) rows.
#define SPITCH 72
#define PLANE  9216          // 128*72 elems
#define STAGE_E 27648        // 3 planes
#define SMEM_DYN 110592      // 2 stages * 27648 * 2B ; epilogue 128*132*4 = 67584 fits

// ---------------- scratch ----------------
__device__ __half g_x16[16777216];
__device__ __half g_y16[ 8388608];
__device__ __half g_w16[  262144];    // kv_w k-rows fp16 [512,512]
__device__ __half g_qw16[ 131072];    // q_w fp16 [512,256]
__device__ __half g_p16[  262144];
__device__ __half g_k16[16777216];
__device__ __half g_q16[16777216];
__device__ __half g_Tth[ 2097152], g_Ttl[ 2097152];
__device__ __half g_M2h[ 2097152], g_M2l[ 2097152];
__device__ float g_nk_part[GNS * BB * CC];
__device__ float g_nq_part[GNS * BB * CC];
__device__ float g_Spart[GNS * BB * HH * DH * DH];
__device__ float g_attn [BB * HH * DH * DH];

// ---------------- helpers ----------------
__device__ __forceinline__ uint32_t smem_u32(const void* p) {
    uint32_t a;
    asm("{ .reg .u64 t; cvta.to.shared.u64 t, %1; cvt.u32.u64 %0, t; }" : "=r"(a) : "l"(p));
    return a;
}
__device__ __forceinline__ void split2h(float v, __half& h, __half& l) {
    h = __float2half_rn(v);
    l = __float2half_rn(v - __half2float(h));
}
__device__ __forceinline__ uint32_t pack2h(__half a, __half b) {
    return (uint32_t)__half_as_ushort(a) | ((uint32_t)__half_as_ushort(b) << 16);
}
#define CPA16(s, g)  asm volatile("cp.async.cg.shared.global [%0], [%1], 16;" :: "r"(s), "l"(g))
#define CPA_COMMIT() asm volatile("cp.async.commit_group;")
#define CPA_WAIT1()  asm volatile("cp.async.wait_group 1;")
#define CPA_WAIT0()  asm volatile("cp.async.wait_group 0;")

// ---------------- conversions ----------------
__global__ void convh_kernel(const float4* __restrict__ in, uint2* __restrict__ o16, int n4) {
    int i = blockIdx.x * 256 + threadIdx.x;
    if (i < n4) {
        float4 v = in[i];
        o16[i] = make_uint2(pack2h(__float2half_rn(v.x), __float2half_rn(v.y)),
                            pack2h(__float2half_rn(v.z), __float2half_rn(v.w)));
    }
}

// ---------------- fp16 split GEMM, CTA 128x128, warp 64x32, K-stage 64 ----------------
// C[m,n] = sum_k A[m,k]*B[n,k]; A fp16; B = Bh (+ Bl if non-null, 2-pass split).
// mode 0: hi/lo fp16 planes. mode 2: fp32 + bias. mode 3: fp16 plane.
__global__ __launch_bounds__(256, 2)
void gemm_wm(const __half* __restrict__ A, int pA, long long sA,
             const __half* __restrict__ Bh, const __half* __restrict__ Bl,
             int pB, long long sB,
             __half* __restrict__ Ch, __half* __restrict__ Cl,
             float* __restrict__ Cf, int pC, long long sC,
             const float* __restrict__ bias, int K, int mode)
{
    extern __shared__ char smraw[];
    __half* sbf = (__half*)smraw;
    float* sf = (float*)smraw;
    const int t = threadIdx.x;
    const int wid = t >> 5;
    const int bz = blockIdx.z;
    const int m0 = blockIdx.y * 128, n0 = blockIdx.x * 128;
    const int wm = (wid & 1) * 64, wn = (wid >> 1) * 32;   // 2x4 warps of 64x32

    const int prow = t >> 3;        // 0..31
    const int pch  = (t & 7) * 8;   // 8-elem (16B) chunk within 64

    const bool twop = (Bl != nullptr);
    const __half* A_  = A  + (long long)bz * sA + (long long)m0 * pA;
    const __half* Bh_ = Bh + (long long)bz * sB + (long long)n0 * pB;
    const __half* Bl_ = twop ? (Bl + (long long)bz * sB + (long long)n0 * pB) : nullptr;

    const int nkb = K >> 6;   // 64-elem stages

    auto produce = [&](int s, int kb) {
        const uint32_t sb = smem_u32(sbf + s * STAGE_E);
        #pragma unroll
        for (int u = 0; u < 4; ++u) {
            const int r = prow + u * 32;
            CPA16(sb + (uint32_t)(r * SPITCH + pch) * 2u,         A_  + (long long)r * pA + kb + pch);
            CPA16(sb + (uint32_t)((r + 128) * SPITCH + pch) * 2u, Bh_ + (long long)r * pB + kb + pch);
            if (twop)
                CPA16(sb + (uint32_t)((r + 256) * SPITCH + pch) * 2u, Bl_ + (long long)r * pB + kb + pch);
        }
        CPA_COMMIT();
    };

    produce(0, 0);

    wmma::fragment<wmma::accumulator, 16, 16, 16, float> acc[4][2];
    #pragma unroll
    for (int i = 0; i < 4; ++i)
        #pragma unroll
        for (int j = 0; j < 2; ++j) wmma::fill_fragment(acc[i][j], 0.0f);

    for (int i = 0; i < nkb; ++i) {
        if (i + 1 < nkb) {
            produce((i + 1) & 1, (i + 1) * 64);
            CPA_WAIT1();
        } else {
            CPA_WAIT0();
        }
        __syncthreads();
        const int s = i & 1;
        const __half* sa  = sbf + s * STAGE_E;
        const __half* sbh = sa + PLANE;
        const __half* sbl = sa + 2 * PLANE;
        #pragma unroll
        for (int kk = 0; kk < 64; kk += 16) {
            wmma::fragment<wmma::matrix_a, 16, 16, 16, __half, wmma::row_major> fa[4];
            wmma::fragment<wmma::matrix_b, 16, 16, 16, __half, wmma::col_major> fbh[2], fbl[2];
            #pragma unroll
            for (int im = 0; im < 4; ++im)
                wmma::load_matrix_sync(fa[im], sa + (wm + im * 16) * SPITCH + kk, SPITCH);
            #pragma unroll
            for (int in_ = 0; in_ < 2; ++in_)
                wmma::load_matrix_sync(fbh[in_], sbh + (wn + in_ * 16) * SPITCH + kk, SPITCH);
            #pragma unroll
            for (int im = 0; im < 4; ++im)
                #pragma unroll
                for (int in_ = 0; in_ < 2; ++in_)
                    wmma::mma_sync(acc[im][in_], fa[im], fbh[in_], acc[im][in_]);
            if (twop) {
                #pragma unroll
                for (int in_ = 0; in_ < 2; ++in_)
                    wmma::load_matrix_sync(fbl[in_], sbl + (wn + in_ * 16) * SPITCH + kk, SPITCH);
                #pragma unroll
                for (int im = 0; im < 4; ++im)
                    #pragma unroll
                    for (int in_ = 0; in_ < 2; ++in_)
                        wmma::mma_sync(acc[im][in_], fa[im], fbl[in_], acc[im][in_]);
            }
        }
        __syncthreads();
    }

    // ---- epilogue via smem (pitch 132) ----
    #pragma unroll
    for (int im = 0; im < 4; ++im)
        #pragma unroll
        for (int in_ = 0; in_ < 2; ++in_)
            wmma::store_matrix_sync(sf + (wm + im * 16) * 132 + wn + in_ * 16,
                                    acc[im][in_], 132, wmma::mem_row_major);
    __syncthreads();

    const int row = t >> 1, half = (t & 1) * 64;
    const float* sr = sf + row * 132 + half;
    if (mode == 0) {
        __half* dh = Ch + (long long)bz * sC + (long long)(m0 + row) * pC + n0 + half;
        __half* dl = Cl + (long long)bz * sC + (long long)(m0 + row) * pC + n0 + half;
        #pragma unroll
        for (int j = 0; j < 8; ++j) {
            uint4 hv, lv;
            uint32_t* hp = (uint32_t*)&hv;
            uint32_t* lp = (uint32_t*)&lv;
            #pragma unroll
            for (int e = 0; e < 4; ++e) {
                __half h0, h1, l0, l1;
                split2h(sr[j * 8 + e * 2 + 0], h0, l0);
                split2h(sr[j * 8 + e * 2 + 1], h1, l1);
                hp[e] = pack2h(h0, h1);
                lp[e] = pack2h(l0, l1);
            }
            *(uint4*)(dh + j * 8) = hv;
            *(uint4*)(dl + j * 8) = lv;
        }
    } else if (mode == 3) {
        __half* dh = Ch + (long long)bz * sC + (long long)(m0 + row) * pC + n0 + half;
        #pragma unroll
        for (int j = 0; j < 8; ++j) {
            uint4 hv;
            uint32_t* hp = (uint32_t*)&hv;
            #pragma unroll
            for (int e = 0; e < 4; ++e)
                hp[e] = pack2h(__float2half_rn(sr[j * 8 + e * 2 + 0]),
                               __float2half_rn(sr[j * 8 + e * 2 + 1]));
            *(uint4*)(dh + j * 8) = hv;
        }
    } else {
        float* dst = Cf + (long long)bz * sC + (long long)(m0 + row) * pC + n0 + half;
        #pragma unroll
        for (int j = 0; j < 16; ++j) {
            float4 v = make_float4(sr[j * 4 + 0], sr[j * 4 + 1], sr[j * 4 + 2], sr[j * 4 + 3]);
            if (mode == 2) {
                const float* bp = bias + n0 + half + j * 4;
                v.x += bp[0]; v.y += bp[1]; v.z += bp[2]; v.w += bp[3];
            }
            *(float4*)(dst + j * 4) = v;
        }
    }
}

// ---------------- tensor-core gram + fused sumsq ----------------
__global__ __launch_bounds__(256) void gram_kernel(
    const __half* __restrict__ q16, const __half* __restrict__ k16,
    float* __restrict__ Spart, float* __restrict__ nq_part, float* __restrict__ nk_part)
{
    const int ns = blockIdx.x, h = blockIdx.y, b = blockIdx.z;
    __shared__ __half qs[64 * 72];
    __shared__ __half ks[64 * 72];
    const int t = threadIdx.x;
    const int wid = t >> 5;
    const int wr = wid & 3, wc = wid >> 2;
    const long long base = ((long long)b * NN) * 512 + h * 64;
    const int n0 = ns * (NN / GNS);

    const int lrow  = t >> 3;
    const int lcol8 = (t & 7) * 8;

    wmma::fragment<wmma::accumulator, 16, 16, 16, float> acc[2];
    wmma::fill_fragment(acc[0], 0.0f);
    wmma::fill_fragment(acc[1], 0.0f);
    float sq_q[8], sq_k[8];
    #pragma unroll
    for (int j = 0; j < 8; ++j) { sq_q[j] = 0.f; sq_k[j] = 0.f; }

    for (int ch = 0; ch < (NN / GNS) / 64; ++ch) {
        const int nb = n0 + ch * 64;
        __syncthreads();
        #pragma unroll
        for (int hf = 0; hf < 2; ++hf) {
            const int r = lrow + hf * 32;
            const long long g = base + (long long)(nb + r) * 512 + lcol8;
            uint4 qv = *(const uint4*)(q16 + g);
            uint4 kv = *(const uint4*)(k16 + g);
            *(uint4*)(qs + r * 72 + lcol8) = qv;
            *(uint4*)(ks + r * 72 + lcol8) = kv;
            const __half* qh_ = (const __half*)&qv;
            const __half* kh_ = (const __half*)&kv;
            #pragma unroll
            for (int j = 0; j < 8; ++j) {
                float fq = __half2float(qh_[j]);
                float fk = __half2float(kh_[j]);
                sq_q[j] += fq * fq;
                sq_k[j] += fk * fk;
            }
        }
        __syncthreads();
        #pragma unroll
        for (int nsub = 0; nsub < 4; ++nsub) {
            wmma::fragment<wmma::matrix_a, 16, 16, 16, __half, wmma::col_major> fa;
            wmma::fragment<wmma::matrix_b, 16, 16, 16, __half, wmma::row_major> fb0, fb1;
            wmma::load_matrix_sync(fa,  qs + nsub * 16 * 72 + wr * 16, 72);
            wmma::load_matrix_sync(fb0, ks + nsub * 16 * 72 + wc * 32, 72);
            wmma::load_matrix_sync(fb1, ks + nsub * 16 * 72 + wc * 32 + 16, 72);
            wmma::mma_sync(acc[0], fa, fb0, acc[0]);
            wmma::mma_sync(acc[1], fa, fb1, acc[1]);
        }
    }

    float* dst = Spart + ((((long long)ns * BB + b) * HH + h) * DH) * DH;
    wmma::store_matrix_sync(dst + (wr * 16) * 64 + wc * 32,      acc[0], 64, wmma::mem_row_major);
    wmma::store_matrix_sync(dst + (wr * 16) * 64 + wc * 32 + 16, acc[1], 64, wmma::mem_row_major);

    __syncthreads();
    float* redq = (float*)qs;
    float* redk = (float*)ks;
    #pragma unroll
    for (int j = 0; j < 8; ++j) { redq[t * 8 + j] = sq_q[j]; redk[t * 8 + j] = sq_k[j]; }
    __syncthreads();
    if (t < 64) {
        const int oct = t >> 3, j = t & 7;
        float sq = 0.f, sk = 0.f;
        #pragma unroll
        for (int m = 0; m < 32; ++m) {
            const int tt = m * 8 + oct;
            sq += redq[tt * 8 + j];
            sk += redk[tt * 8 + j];
        }
        nq_part[(ns * BB + b) * CC + h * 64 + t] = sq;
        nk_part[(ns * BB + b) * CC + h * 64 + t] = sk;
    }
}

// ---------------- attn ----------------
__global__ void attn_kernel(
    const float* __restrict__ Spart,
    const float* __restrict__ nq_part, const float* __restrict__ nk_part,
    const float* __restrict__ temp, float* __restrict__ attn)
{
    const int h = blockIdx.x, b = blockIdx.y, d = threadIdx.x;
    __shared__ float snk[64];
    const int c = h * 64 + d;
    float sk = 0.f, sq = 0.f;
    #pragma unroll
    for (int ch = 0; ch < GNS; ++ch) {
        sk += nk_part[(ch * BB + b) * CC + c];
        sq += nq_part[(ch * BB + b) * CC + c];
    }
    snk[d] = fmaxf(sqrtf(sk), EPSF);
    const float nqv = fmaxf(sqrtf(sq), EPSF);
    __syncthreads();
    const float tv = temp[h];
    float vals[64];
    float mx = -1e30f;
    #pragma unroll
    for (int e = 0; e < 64; ++e) {
        float s = 0.f;
        #pragma unroll
        for (int ns = 0; ns < GNS; ++ns)
            s += Spart[((((long long)ns * BB + b) * HH + h) * DH + d) * DH + e];
        float v = s * tv / (nqv * snk[e]);
        vals[e] = v;
        mx = fmaxf(mx, v);
    }
    float sum = 0.f;
    #pragma unroll
    for (int e = 0; e < 64; ++e) { vals[e] = expf(vals[e] - mx); sum += vals[e]; }
    const float inv = 1.0f / sum;
    float* row = attn + (((long long)(b * HH + h) * DH) * DH) + (long long)d * DH;
    #pragma unroll
    for (int e = 0; e < 64; ++e) row[e] = vals[e] * inv;
}

// ---------------- tkern ----------------
__global__ __launch_bounds__(256) void tkern(
    const float* __restrict__ attn, const float* __restrict__ kv_w,
    __half* __restrict__ Tth, __half* __restrict__ Ttl)
{
    const int b = blockIdx.x, h = blockIdx.y;
    __shared__ float AT[64][65];
    const float* Ab = attn + (((long long)(b * HH + h) * DH) * DH);
    for (int i = threadIdx.x; i < 4096; i += 256) AT[i >> 6][i & 63] = Ab[i];
    __syncthreads();
    const float* Wv = kv_w + (long long)(512 + h * 64) * CC;
    for (int half_ = 0; half_ < 2; ++half_) {
        const int c = half_ * 256 + threadIdx.x;
        float acc[64];
        #pragma unroll
        for (int d = 0; d < 64; ++d) acc[d] = 0.f;
        for (int e = 0; e < 64; ++e) {
            const float wv = Wv[(long long)e * CC + c];
            #pragma unroll
            for (int d = 0; d < 64; ++d) acc[d] += AT[d][e] * wv;
        }
        const long long base = ((long long)b * CC + c) * CC + h * 64;
        #pragma unroll
        for (int d = 0; d < 64; d += 2) {
            __half h0, l0, h1, l1;
            split2h(acc[d],     h0, l0);
            split2h(acc[d + 1], h1, l1);
            *(uint32_t*)(Tth + base + d) = pack2h(h0, h1);
            *(uint32_t*)(Ttl + base + d) = pack2h(l0, l1);
        }
    }
}

// ---------------- launch ----------------
extern "C" void kernel_launch(void* const* d_in, const int* in_sizes, int n_in,
                              void* d_out, int out_size)
{
    (void)in_sizes; (void)n_in; (void)out_size;
    const float* x      = (const float*)d_in[0];
    const float* y      = (const float*)d_in[1];
    const float* kv_w   = (const float*)d_in[2];
    const float* q_w    = (const float*)d_in[3];
    const float* proj_w = (const float*)d_in[4];
    const float* proj_b = (const float*)d_in[5];
    const float* temp   = (const float*)d_in[6];
    float* out = (float*)d_out;

    __half *x16, *y16, *w16, *qw16, *p16, *k16, *q16, *Tth, *Ttl, *M2h, *M2l;
    float *nkp, *nqp, *Sp, *ap;
    cudaGetSymbolAddress((void**)&x16,  g_x16);
    cudaGetSymbolAddress((void**)&y16,  g_y16);
    cudaGetSymbolAddress((void**)&w16,  g_w16);
    cudaGetSymbolAddress((void**)&qw16, g_qw16);
    cudaGetSymbolAddress((void**)&p16,  g_p16);
    cudaGetSymbolAddress((void**)&k16,  g_k16);
    cudaGetSymbolAddress((void**)&q16,  g_q16);
    cudaGetSymbolAddress((void**)&Tth,  g_Tth); cudaGetSymbolAddress((void**)&Ttl, g_Ttl);
    cudaGetSymbolAddress((void**)&M2h,  g_M2h); cudaGetSymbolAddress((void**)&M2l, g_M2l);
    cudaGetSymbolAddress((void**)&nkp,  g_nk_part);
    cudaGetSymbolAddress((void**)&nqp,  g_nq_part);
    cudaGetSymbolAddress((void**)&Sp,   g_Spart);
    cudaGetSymbolAddress((void**)&ap,   g_attn);

    cudaFuncSetAttribute(gemm_wm, cudaFuncAttributeMaxDynamicSharedMemorySize, SMEM_DYN);

    // 0) conversions
    convh_kernel<<<16384, 256>>>((const float4*)x,      (uint2*)x16,  4194304);
    convh_kernel<<< 8192, 256>>>((const float4*)y,      (uint2*)y16,  2097152);
    convh_kernel<<<  256, 256>>>((const float4*)proj_w, (uint2*)p16,    65536);
    convh_kernel<<<  256, 256>>>((const float4*)kv_w,   (uint2*)w16,    65536);  // k rows only
    convh_kernel<<<  128, 256>>>((const float4*)q_w,    (uint2*)qw16,   32768);

    // 1) k = x @ Wk^T -> fp16   (single pass: logit path)
    gemm_wm<<<dim3(4, 256, 1), 256, SMEM_DYN>>>(
        x16, 512, 0, w16, nullptr, 512, 0,
        k16, nullptr, nullptr, 512, 0, nullptr, 512, 3);

    // 2) q = y @ q_w^T -> fp16  (single pass)
    gemm_wm<<<dim3(4, 256, 1), 256, SMEM_DYN>>>(
        y16, 256, 0, qw16, nullptr, 256, 0,
        q16, nullptr, nullptr, 512, 0, nullptr, 256, 3);

    // 3) tensor-core Gram + fused sumsq
    gram_kernel<<<dim3(GNS, HH, BB), 256>>>(q16, k16, Sp, nqp, nkp);

    // 4) normalize + softmax
    attn_kernel<<<dim3(HH, BB), 64>>>(Sp, nqp, nkp, temp, ap);

    // 5) Tt (fp32 attn x fp32 Wv -> hi/lo planes)
    tkern<<<dim3(BB, HH), 256>>>(ap, kv_w, Tth, Ttl);

    // 6) M2 = proj_w @ Tt^T -> fp16 hi/lo (2-pass, unchanged from R13)
    gemm_wm<<<dim3(4, 4, BB), 256, SMEM_DYN>>>(
        p16, 512, 0,
        Tth, Ttl, 512, (long long)CC * CC,
        M2h, M2l, nullptr, 512, (long long)CC * CC, nullptr, 512, 0);

    // 7) out = x @ M2h^T + bias -> fp32 (SINGLE pass — the only change vs R13)
    gemm_wm<<<dim3(4, 32, BB), 256, SMEM_DYN>>>(
        x16, 512, (long long)NN * 512,
        M2h, nullptr, 512, (long long)CC * CC,
        nullptr, nullptr, out, 512, (long long)NN * CC,
        proj_b, 512, 2);
}